// round 4
// baseline (speedup 1.0000x reference)
#include <cuda_runtime.h>
#include <cstdint>

// Problem constants (shapes fixed by the dataset problem)
#define ROWS 64            // B*N
#define PP   147456        // H*W
#define KCLS 3
#define NBIN 4096
#define CHUNKS 16
#define CHUNK  (PP / CHUNKS)          // 9216
#define THREADS 256
#define ITERS   (CHUNK / (THREADS*4)) // 9

#define CNT_SHIFT 46
#define FX_SCALE  4194304.0f          // 2^22 per-element fixed point
#define FX_MASK   ((1ull << CNT_SHIFT) - 1ull)
#define TOT_MUL   256ull              // 2^22 -> 2^30 for g_total
#define FXD       1073741824.0        // 2^30

// -------- scratch (no allocations allowed; device globals) --------
__device__ float g_nll [(size_t)ROWS * PP];
__device__ float g_side[(size_t)ROWS * PP];
__device__ unsigned long long g_hist[ROWS * NBIN];   // (count<<46) | fxsum
__device__ unsigned int g_sidecnt[ROWS];
__device__ int g_bstar[ROWS];
__device__ int g_needed[ROWS];
__device__ int g_m;
__device__ unsigned long long g_total;               // 2^30 fixed point

__device__ __forceinline__ unsigned int nbits(float v) {
    return (v > 0.0f) ? __float_as_uint(v) : 0u;     // nll >= 0
}

__device__ __forceinline__ unsigned long long pack_elem(float v) {
    // saturate at 64.0 so 147456 * fx never overflows 46 bits
    float c = fminf(v, 64.0f);
    unsigned long long fx = (unsigned long long)(c * FX_SCALE + 0.5f);
    return (1ull << CNT_SHIFT) | fx;
}

__device__ __forceinline__ float nllsel(int t, float a, float b, float c) {
    if (t == 255) return 0.0f;                       // ignore_index
    float v = (t == 0) ? a : (t == 1) ? b : c;
    return -v;
}

// -------- K0: zero scratch, decode step_percent -> m --------
__global__ void k0_init(const void* sp_ptr, int has_sp) {
    int i = blockIdx.x * blockDim.x + threadIdx.x;
    for (; i < ROWS * NBIN; i += gridDim.x * blockDim.x) g_hist[i] = 0ull;
    if (blockIdx.x == 0) {
        if (threadIdx.x < ROWS) g_sidecnt[threadIdx.x] = 0u;
        if (threadIdx.x == 0) {
            g_total = 0ull;
            double sp = 1.0;
            if (has_sp) {
                unsigned int bits = *(const unsigned int*)sp_ptr;
                if (bits < 1024u) sp = (double)(int)bits;            // int32 scalar
                else              sp = (double)__uint_as_float(bits);// float32 scalar
            }
            if (sp > 1.0) sp = 1.0;
            if (sp < 0.0) sp = 0.0;
            double md = sp * 0.15 * (double)PP + (1.0 - sp) * (double)PP;
            int m = (int)md;
            if (m < 1) m = 1;
            if (m > PP) m = PP;
            g_m = m;
        }
    }
}

// -------- K1: nll compute + buffer + per-row count+sum histogram --------
__global__ void __launch_bounds__(THREADS) k1_nll(const float* __restrict__ inp,
                                                  const int*   __restrict__ tgt) {
    __shared__ unsigned long long sh[NBIN];          // 32 KB
    for (int i = threadIdx.x; i < NBIN; i += THREADS) sh[i] = 0ull;
    __syncthreads();

    int row = blockIdx.x / CHUNKS;
    int seg = blockIdx.x % CHUNKS;
    size_t tbase = (size_t)row * PP + (size_t)seg * CHUNK;
    const float* p0 = inp + (size_t)row * KCLS * PP + (size_t)seg * CHUNK;
    const float* p1 = p0 + PP;
    const float* p2 = p0 + 2 * PP;
    const int*   tg = tgt + tbase;
    float*       ob = g_nll + tbase;

#pragma unroll
    for (int it = 0; it < ITERS; ++it) {
        int off = it * (THREADS * 4) + threadIdx.x * 4;
        int4   t4 = *(const int4*)(tg + off);
        float4 a  = *(const float4*)(p0 + off);
        float4 b  = *(const float4*)(p1 + off);
        float4 c  = *(const float4*)(p2 + off);
        float4 o;
        o.x = nllsel(t4.x, a.x, b.x, c.x);
        o.y = nllsel(t4.y, a.y, b.y, c.y);
        o.z = nllsel(t4.z, a.z, b.z, c.z);
        o.w = nllsel(t4.w, a.w, b.w, c.w);
        atomicAdd(&sh[nbits(o.x) >> 19], pack_elem(o.x));
        atomicAdd(&sh[nbits(o.y) >> 19], pack_elem(o.y));
        atomicAdd(&sh[nbits(o.z) >> 19], pack_elem(o.z));
        atomicAdd(&sh[nbits(o.w) >> 19], pack_elem(o.w));
        *(float4*)(ob + off) = o;
    }
    __syncthreads();
    for (int i = threadIdx.x; i < NBIN; i += THREADS) {
        unsigned long long v = sh[i];
        if (v) atomicAdd(&g_hist[row * NBIN + i], v);
    }
}

// -------- K2: per-row threshold bin + exact above-threshold sum --------
__global__ void __launch_bounds__(THREADS) k2_thresh() {
    int row = blockIdx.x;
    __shared__ unsigned long long sh[NBIN];          // 32 KB
    __shared__ unsigned int cs[THREADS];
    __shared__ unsigned long long ss[THREADS];
    for (int i = threadIdx.x; i < NBIN; i += THREADS)
        sh[i] = g_hist[row * NBIN + i];
    __syncthreads();
    unsigned c = 0; unsigned long long s = 0ull;
    int base = threadIdx.x * (NBIN / THREADS);       // 16 bins each
    for (int j = 0; j < NBIN / THREADS; ++j) {
        unsigned long long v = sh[base + j];
        c += (unsigned)(v >> CNT_SHIFT);
        s += (v & FX_MASK);
    }
    cs[threadIdx.x] = c;
    ss[threadIdx.x] = s;
    __syncthreads();
    if (threadIdx.x == 0) {
        unsigned m = (unsigned)g_m;
        unsigned acc = 0, above = 0;
        unsigned long long sum_fx = 0ull;
        int bstar = 0;
        for (int j = THREADS - 1; j >= 0; --j) {
            if (acc + cs[j] >= m) {
                for (int b = j * 16 + 15; b >= j * 16; --b) {
                    unsigned long long v = sh[b];
                    unsigned bc = (unsigned)(v >> CNT_SHIFT);
                    acc += bc;
                    if (acc >= m) { bstar = b; above = acc - bc; break; }
                    sum_fx += (v & FX_MASK);
                }
                break;
            }
            acc += cs[j];
            sum_fx += ss[j];
        }
        g_bstar[row]  = bstar;
        g_needed[row] = (int)m - (int)above;
        if (sum_fx) atomicAdd(&g_total, sum_fx * TOT_MUL);
    }
}

// -------- K3: pure filter pass — compact threshold-bin values --------
__global__ void __launch_bounds__(THREADS) k3_filter() {
    int row = blockIdx.x / CHUNKS;
    int seg = blockIdx.x % CHUNKS;
    unsigned bstar = (unsigned)g_bstar[row];
    size_t tbase = (size_t)row * PP + (size_t)seg * CHUNK;
    const float* ib = g_nll + tbase;
    float* sb = g_side + (size_t)row * PP;
    int lane = threadIdx.x & 31;

#pragma unroll
    for (int it = 0; it < ITERS; ++it) {
        int off = it * (THREADS * 4) + threadIdx.x * 4;
        float4 v = *(const float4*)(ib + off);
        float vv[4] = {v.x, v.y, v.z, v.w};
#pragma unroll
        for (int e = 0; e < 4; ++e) {
            bool q = ((nbits(vv[e]) >> 19) == bstar);
            unsigned bal = __ballot_sync(0xffffffffu, q);
            if (bal) {
                unsigned base;
                int leader = __ffs(bal) - 1;
                if (lane == leader)
                    base = atomicAdd(&g_sidecnt[row], (unsigned)__popc(bal));
                base = __shfl_sync(0xffffffffu, base, leader);
                if (q) sb[base + __popc(bal & ((1u << lane) - 1u))] = vv[e];
            }
        }
    }
}

// -------- K4: exact select inside the threshold bin (2 radix levels) --------
__global__ void __launch_bounds__(THREADS) k4_side() {
    int row = blockIdx.x;
    int needed = g_needed[row];
    if (needed <= 0) return;
    int cnt = (int)g_sidecnt[row];
    const float* sb = g_side + (size_t)row * PP;
    int tid = threadIdx.x;

    __shared__ unsigned int h[NBIN];
    __shared__ unsigned int cs[THREADS];
    __shared__ unsigned long long red[THREADS];
    __shared__ unsigned int hb[128];
    __shared__ int s_b2, s_need2, s_b3, s_need3;

    for (int i = tid; i < NBIN; i += THREADS) h[i] = 0u;
    __syncthreads();
    for (int i = tid; i < cnt; i += THREADS) {
        unsigned bits = nbits(sb[i]);
        atomicAdd(&h[(bits >> 7) & 0xFFFu], 1u);
    }
    __syncthreads();
    unsigned s = 0;
    int base = tid * (NBIN / THREADS);
    for (int j = 0; j < NBIN / THREADS; ++j) s += h[base + j];
    cs[tid] = s;
    __syncthreads();
    if (tid == 0) {
        unsigned acc = 0, above = 0; int b2 = 0;
        for (int j = THREADS - 1; j >= 0; --j) {
            if (acc + cs[j] >= (unsigned)needed) {
                for (int b = j * 16 + 15; b >= j * 16; --b) {
                    acc += h[b];
                    if (acc >= (unsigned)needed) { b2 = b; above = acc - h[b]; break; }
                }
                break;
            }
            acc += cs[j];
        }
        s_b2 = b2; s_need2 = needed - (int)above;
    }
    for (int i = tid; i < 128; i += THREADS) hb[i] = 0u;
    __syncthreads();
    int b2 = s_b2, need2 = s_need2;

    unsigned long long sum1 = 0ull;
    for (int i = tid; i < cnt; i += THREADS) {
        float v = sb[i];
        unsigned bits = nbits(v);
        int b = (int)((bits >> 7) & 0xFFFu);
        if (b > b2) sum1 += (pack_elem(v) & FX_MASK);
        else if (b == b2) atomicAdd(&hb[bits & 0x7Fu], 1u);
    }
    red[tid] = sum1;
    __syncthreads();
    for (int st = THREADS / 2; st > 0; st >>= 1) {
        if (tid < st) red[tid] += red[tid + st];
        __syncthreads();
    }
    unsigned long long sum_gt2 = red[0];   // read by all before next barrier pass
    if (tid == 0) {
        unsigned acc = 0, above = 0; int b3 = 0;
        for (int b = 127; b >= 0; --b) {
            acc += hb[b];
            if (acc >= (unsigned)need2) { b3 = b; above = acc - hb[b]; break; }
        }
        s_b3 = b3; s_need3 = need2 - (int)above;
    }
    __syncthreads();
    int b3 = s_b3, need3 = s_need3;

    unsigned long long sum2 = 0ull;
    for (int i = tid; i < cnt; i += THREADS) {
        float v = sb[i];
        unsigned bits = nbits(v);
        if ((int)((bits >> 7) & 0xFFFu) == b2 && (int)(bits & 0x7Fu) > b3)
            sum2 += (pack_elem(v) & FX_MASK);
    }
    red[tid] = sum2;
    __syncthreads();
    for (int st = THREADS / 2; st > 0; st >>= 1) {
        if (tid < st) red[tid] += red[tid + st];
        __syncthreads();
    }
    if (tid == 0) {
        unsigned tb = ((unsigned)g_bstar[row] << 19) | ((unsigned)b2 << 7) | (unsigned)b3;
        float tv = __uint_as_float(tb);
        unsigned long long tv_fx = pack_elem(tv) & FX_MASK;
        unsigned long long contrib = sum_gt2 + red[0]
                                   + (unsigned long long)need3 * tv_fx;
        if (contrib) atomicAdd(&g_total, contrib * TOT_MUL);
    }
}

// -------- K5: finalize mean --------
__global__ void k5_final(float* out) {
    if (threadIdx.x == 0 && blockIdx.x == 0) {
        double tot = (double)g_total / FXD;
        out[0] = (float)(tot / ((double)ROWS * (double)g_m));
    }
}

extern "C" void kernel_launch(void* const* d_in, const int* in_sizes, int n_in,
                              void* d_out, int out_size) {
    const float* inp = (const float*)d_in[0];
    const int*   tgt = (const int*)d_in[1];
    const void*  sp  = (n_in > 2) ? d_in[2] : nullptr;
    (void)in_sizes; (void)out_size;

    k0_init<<<256, THREADS>>>(sp, (n_in > 2) ? 1 : 0);
    k1_nll<<<ROWS * CHUNKS, THREADS>>>(inp, tgt);
    k2_thresh<<<ROWS, THREADS>>>();
    k3_filter<<<ROWS * CHUNKS, THREADS>>>();
    k4_side<<<ROWS, THREADS>>>();
    k5_final<<<1, 32>>>((float*)d_out);
}

// round 6
// speedup vs baseline: 1.2376x; 1.2376x over previous
#include <cuda_runtime.h>
#include <cstdint>

// Problem constants (shapes fixed by the dataset problem)
#define ROWS 64            // B*N
#define PP   147456        // H*W
#define KCLS 3
#define NBIN 4096
#define CHUNKS 16
#define CHUNK  (PP / CHUNKS)          // 9216
#define THREADS 256
#define ITERS   (CHUNK / (THREADS*4)) // 9

#define FX_SCALE  4194304.0f          // 2^22 per-element fixed point
#define TOT_MUL   256ull              // 2^22 -> 2^30 for g_total
#define FXD       1073741824.0        // 2^30

// -------- scratch (no allocations allowed; device globals) --------
__device__ float g_nll [(size_t)ROWS * PP];
__device__ float g_side[(size_t)ROWS * PP];
__device__ unsigned int g_hist[ROWS * NBIN];
__device__ unsigned int g_sidecnt[ROWS];
__device__ int g_bstar[ROWS];
__device__ int g_needed[ROWS];
__device__ int g_m;
__device__ unsigned long long g_total;               // 2^30 fixed point

__device__ __forceinline__ unsigned int nbits(float v) {
    return (v > 0.0f) ? __float_as_uint(v) : 0u;     // nll >= 0
}

__device__ __forceinline__ unsigned long long fx_of(float v) {
    float c = fminf(v, 64.0f);                       // 46-bit safety cap
    return (unsigned long long)(c * FX_SCALE + 0.5f);
}

__device__ __forceinline__ float nllsel(int t, float a, float b, float c) {
    if (t == 255) return 0.0f;                       // ignore_index
    float v = (t == 0) ? a : (t == 1) ? b : c;
    return -v;
}

// -------- K0: zero scratch, decode step_percent -> m --------
__global__ void k0_init(const void* sp_ptr, int has_sp) {
    int i = blockIdx.x * blockDim.x + threadIdx.x;
    for (; i < ROWS * NBIN; i += gridDim.x * blockDim.x) g_hist[i] = 0u;
    if (blockIdx.x == 0) {
        if (threadIdx.x < ROWS) g_sidecnt[threadIdx.x] = 0u;
        if (threadIdx.x == 0) {
            g_total = 0ull;
            double sp = 1.0;
            if (has_sp) {
                unsigned int bits = *(const unsigned int*)sp_ptr;
                if (bits < 1024u) sp = (double)(int)bits;            // int32 scalar
                else              sp = (double)__uint_as_float(bits);// float32 scalar
            }
            if (sp > 1.0) sp = 1.0;
            if (sp < 0.0) sp = 0.0;
            double md = sp * 0.15 * (double)PP + (1.0 - sp) * (double)PP;
            int m = (int)md;
            if (m < 1) m = 1;
            if (m > PP) m = PP;
            g_m = m;
        }
    }
}

// -------- K1: nll compute + buffer + per-row u32 histogram --------
__global__ void __launch_bounds__(THREADS) k1_nll(const float* __restrict__ inp,
                                                  const int*   __restrict__ tgt) {
    __shared__ unsigned int sh[NBIN];                // 16 KB
    for (int i = threadIdx.x; i < NBIN; i += THREADS) sh[i] = 0u;
    __syncthreads();

    int row = blockIdx.x / CHUNKS;
    int seg = blockIdx.x % CHUNKS;
    size_t tbase = (size_t)row * PP + (size_t)seg * CHUNK;
    const float* p0 = inp + (size_t)row * KCLS * PP + (size_t)seg * CHUNK;
    const float* p1 = p0 + PP;
    const float* p2 = p0 + 2 * PP;
    const int*   tg = tgt + tbase;
    float*       ob = g_nll + tbase;

    int off0 = threadIdx.x * 4;
    // double-buffered loads for MLP
    int4   t4 = *(const int4*)(tg + off0);
    float4 a  = *(const float4*)(p0 + off0);
    float4 b  = *(const float4*)(p1 + off0);
    float4 c  = *(const float4*)(p2 + off0);

#pragma unroll
    for (int it = 0; it < ITERS; ++it) {
        int4 t4n; float4 an, bn, cn;
        if (it + 1 < ITERS) {
            int offn = (it + 1) * (THREADS * 4) + threadIdx.x * 4;
            t4n = *(const int4*)(tg + offn);
            an  = *(const float4*)(p0 + offn);
            bn  = *(const float4*)(p1 + offn);
            cn  = *(const float4*)(p2 + offn);
        }
        int off = it * (THREADS * 4) + threadIdx.x * 4;
        float4 o;
        o.x = nllsel(t4.x, a.x, b.x, c.x);
        o.y = nllsel(t4.y, a.y, b.y, c.y);
        o.z = nllsel(t4.z, a.z, b.z, c.z);
        o.w = nllsel(t4.w, a.w, b.w, c.w);
        atomicAdd(&sh[nbits(o.x) >> 19], 1u);
        atomicAdd(&sh[nbits(o.y) >> 19], 1u);
        atomicAdd(&sh[nbits(o.z) >> 19], 1u);
        atomicAdd(&sh[nbits(o.w) >> 19], 1u);
        *(float4*)(ob + off) = o;
        t4 = t4n; a = an; b = bn; c = cn;
    }
    __syncthreads();
    for (int i = threadIdx.x; i < NBIN; i += THREADS) {
        unsigned int v = sh[i];
        if (v) atomicAdd(&g_hist[row * NBIN + i], v);
    }
}

// -------- K2: per-row threshold bin via suffix scan (counts only) --------
__global__ void __launch_bounds__(THREADS) k2_thresh() {
    int row = blockIdx.x;
    __shared__ unsigned int sh[NBIN];
    __shared__ unsigned int cs[THREADS];
    for (int i = threadIdx.x; i < NBIN; i += THREADS)
        sh[i] = g_hist[row * NBIN + i];
    __syncthreads();
    unsigned s = 0;
    int base = threadIdx.x * (NBIN / THREADS);       // 16 bins each
    for (int j = 0; j < NBIN / THREADS; ++j) s += sh[base + j];
    cs[threadIdx.x] = s;
    __syncthreads();
    if (threadIdx.x == 0) {
        unsigned m = (unsigned)g_m;
        unsigned acc = 0, above = 0;
        int bstar = 0;
        for (int j = THREADS - 1; j >= 0; --j) {
            if (acc + cs[j] >= m) {
                for (int b = j * 16 + 15; b >= j * 16; --b) {
                    acc += sh[b];
                    if (acc >= m) { bstar = b; above = acc - sh[b]; break; }
                }
                break;
            }
            acc += cs[j];
        }
        g_bstar[row]  = bstar;
        g_needed[row] = (int)m - (int)above;
    }
}

// -------- K3: batched stream — fx-sum above bins, compact threshold bin --------
__global__ void __launch_bounds__(THREADS) k3_sum() {
    int row = blockIdx.x / CHUNKS;
    int seg = blockIdx.x % CHUNKS;
    unsigned bstar = (unsigned)g_bstar[row];
    size_t tbase = (size_t)row * PP + (size_t)seg * CHUNK;
    const float4* ib = (const float4*)(g_nll + tbase);
    float* sb = g_side + (size_t)row * PP;

    // Front-batch all loads: 9 independent LDG.128 in flight per warp.
    float4 r[ITERS];
#pragma unroll
    for (int it = 0; it < ITERS; ++it)
        r[it] = ib[it * THREADS + threadIdx.x];

    unsigned long long fx = 0ull;
#pragma unroll
    for (int it = 0; it < ITERS; ++it) {
        float vv[4] = {r[it].x, r[it].y, r[it].z, r[it].w};
#pragma unroll
        for (int e = 0; e < 4; ++e) {
            float v = vv[e];
            unsigned bin = nbits(v) >> 19;
            if (bin > bstar) {
                fx += fx_of(v);
            } else if (bin == bstar) {               // rare (~2%)
                unsigned idx = atomicAdd(&g_sidecnt[row], 1u);
                sb[idx] = v;
            }
        }
    }

    __shared__ unsigned long long red[THREADS];
    red[threadIdx.x] = fx;
    __syncthreads();
    for (int st = THREADS / 2; st > 0; st >>= 1) {
        if (threadIdx.x < st) red[threadIdx.x] += red[threadIdx.x + st];
        __syncthreads();
    }
    if (threadIdx.x == 0 && red[0])
        atomicAdd(&g_total, red[0] * TOT_MUL);
}

// -------- K4: exact select inside the threshold bin (2 radix levels) --------
__global__ void __launch_bounds__(THREADS) k4_side() {
    int row = blockIdx.x;
    int needed = g_needed[row];
    if (needed <= 0) return;
    int cnt = (int)g_sidecnt[row];
    const float* sb = g_side + (size_t)row * PP;
    int tid = threadIdx.x;

    __shared__ unsigned int h[NBIN];
    __shared__ unsigned int cs[THREADS];
    __shared__ unsigned long long red[THREADS];
    __shared__ unsigned int hb[128];
    __shared__ int s_b2, s_need2, s_b3, s_need3;

    for (int i = tid; i < NBIN; i += THREADS) h[i] = 0u;
    __syncthreads();
    for (int i = tid; i < cnt; i += THREADS) {
        unsigned bits = nbits(sb[i]);
        atomicAdd(&h[(bits >> 7) & 0xFFFu], 1u);
    }
    __syncthreads();
    unsigned s = 0;
    int base = tid * (NBIN / THREADS);
    for (int j = 0; j < NBIN / THREADS; ++j) s += h[base + j];
    cs[tid] = s;
    __syncthreads();
    if (tid == 0) {
        unsigned acc = 0, above = 0; int b2 = 0;
        for (int j = THREADS - 1; j >= 0; --j) {
            if (acc + cs[j] >= (unsigned)needed) {
                for (int b = j * 16 + 15; b >= j * 16; --b) {
                    acc += h[b];
                    if (acc >= (unsigned)needed) { b2 = b; above = acc - h[b]; break; }
                }
                break;
            }
            acc += cs[j];
        }
        s_b2 = b2; s_need2 = needed - (int)above;
    }
    for (int i = tid; i < 128; i += THREADS) hb[i] = 0u;
    __syncthreads();
    int b2 = s_b2, need2 = s_need2;

    unsigned long long sum1 = 0ull;
    for (int i = tid; i < cnt; i += THREADS) {
        float v = sb[i];
        unsigned bits = nbits(v);
        int b = (int)((bits >> 7) & 0xFFFu);
        if (b > b2) sum1 += fx_of(v);
        else if (b == b2) atomicAdd(&hb[bits & 0x7Fu], 1u);
    }
    red[tid] = sum1;
    __syncthreads();
    for (int st = THREADS / 2; st > 0; st >>= 1) {
        if (tid < st) red[tid] += red[tid + st];
        __syncthreads();
    }
    unsigned long long sum_gt2 = red[0];   // read by all before next barrier pass
    if (tid == 0) {
        unsigned acc = 0, above = 0; int b3 = 0;
        for (int b = 127; b >= 0; --b) {
            acc += hb[b];
            if (acc >= (unsigned)need2) { b3 = b; above = acc - hb[b]; break; }
        }
        s_b3 = b3; s_need3 = need2 - (int)above;
    }
    __syncthreads();
    int b3 = s_b3, need3 = s_need3;

    unsigned long long sum2 = 0ull;
    for (int i = tid; i < cnt; i += THREADS) {
        float v = sb[i];
        unsigned bits = nbits(v);
        if ((int)((bits >> 7) & 0xFFFu) == b2 && (int)(bits & 0x7Fu) > b3)
            sum2 += fx_of(v);
    }
    red[tid] = sum2;
    __syncthreads();
    for (int st = THREADS / 2; st > 0; st >>= 1) {
        if (tid < st) red[tid] += red[tid + st];
        __syncthreads();
    }
    if (tid == 0) {
        unsigned tb = ((unsigned)g_bstar[row] << 19) | ((unsigned)b2 << 7) | (unsigned)b3;
        float tv = __uint_as_float(tb);
        unsigned long long contrib = sum_gt2 + red[0]
                                   + (unsigned long long)need3 * fx_of(tv);
        if (contrib) atomicAdd(&g_total, contrib * TOT_MUL);
    }
}

// -------- K5: finalize mean --------
__global__ void k5_final(float* out) {
    if (threadIdx.x == 0 && blockIdx.x == 0) {
        double tot = (double)g_total / FXD;
        out[0] = (float)(tot / ((double)ROWS * (double)g_m));
    }
}

extern "C" void kernel_launch(void* const* d_in, const int* in_sizes, int n_in,
                              void* d_out, int out_size) {
    const float* inp = (const float*)d_in[0];
    const int*   tgt = (const int*)d_in[1];
    const void*  sp  = (n_in > 2) ? d_in[2] : nullptr;
    (void)in_sizes; (void)out_size;

    k0_init<<<256, THREADS>>>(sp, (n_in > 2) ? 1 : 0);
    k1_nll<<<ROWS * CHUNKS, THREADS>>>(inp, tgt);
    k2_thresh<<<ROWS, THREADS>>>();
    k3_sum<<<ROWS * CHUNKS, THREADS>>>();
    k4_side<<<ROWS, THREADS>>>();
    k5_final<<<1, 32>>>((float*)d_out);
}

// round 7
// speedup vs baseline: 2.1606x; 1.7458x over previous
#include <cuda_runtime.h>
#include <cstdint>

// Problem constants (shapes fixed by the dataset problem)
#define ROWS 64            // B*N
#define PP   147456        // H*W
#define KCLS 3
#define NBIN 4096
#define CHUNKS 16
#define CHUNK  (PP / CHUNKS)          // 9216
#define THREADS 256
#define ITERS   (CHUNK / (THREADS*4)) // 9

#define FX_SCALE  4194304.0f          // 2^22 per-element fixed point
#define TOT_MUL   256ull              // 2^22 -> 2^30 for g_total
#define FXD       1073741824.0        // 2^30

// -------- scratch (no allocations allowed; device globals) --------
__device__ float g_nll [(size_t)ROWS * PP];
__device__ float g_side[(size_t)ROWS * PP];          // segmented: (row*CHUNKS+seg)*CHUNK
__device__ unsigned int g_hist[ROWS * NBIN];
__device__ unsigned int g_segcnt[ROWS * CHUNKS];
__device__ int g_bstar[ROWS];
__device__ int g_needed[ROWS];
__device__ int g_m;
__device__ unsigned long long g_total;               // 2^30 fixed point

__device__ __forceinline__ unsigned int nbits(float v) {
    return (v > 0.0f) ? __float_as_uint(v) : 0u;     // nll >= 0
}

__device__ __forceinline__ unsigned long long fx_of(float v) {
    float c = fminf(v, 64.0f);                       // 46-bit safety cap
    return (unsigned long long)(c * FX_SCALE + 0.5f);
}

__device__ __forceinline__ float nllsel(int t, float a, float b, float c) {
    if (t == 255) return 0.0f;                       // ignore_index
    float v = (t == 0) ? a : (t == 1) ? b : c;
    return -v;
}

// -------- K0: zero scratch, decode step_percent -> m --------
__global__ void k0_init(const void* sp_ptr, int has_sp) {
    int i = blockIdx.x * blockDim.x + threadIdx.x;
    for (; i < ROWS * NBIN; i += gridDim.x * blockDim.x) g_hist[i] = 0u;
    if (blockIdx.x == 0) {
        if (threadIdx.x == 0) {
            g_total = 0ull;
            double sp = 1.0;
            if (has_sp) {
                unsigned int bits = *(const unsigned int*)sp_ptr;
                if (bits < 1024u) sp = (double)(int)bits;            // int32 scalar
                else              sp = (double)__uint_as_float(bits);// float32 scalar
            }
            if (sp > 1.0) sp = 1.0;
            if (sp < 0.0) sp = 0.0;
            double md = sp * 0.15 * (double)PP + (1.0 - sp) * (double)PP;
            int m = (int)md;
            if (m < 1) m = 1;
            if (m > PP) m = PP;
            g_m = m;
        }
    }
}

// -------- K1: nll compute + buffer + per-row u32 histogram --------
__global__ void __launch_bounds__(THREADS) k1_nll(const float* __restrict__ inp,
                                                  const int*   __restrict__ tgt) {
    __shared__ unsigned int sh[NBIN];                // 16 KB
    for (int i = threadIdx.x; i < NBIN; i += THREADS) sh[i] = 0u;
    __syncthreads();

    int row = blockIdx.x / CHUNKS;
    int seg = blockIdx.x % CHUNKS;
    size_t tbase = (size_t)row * PP + (size_t)seg * CHUNK;
    const float* p0 = inp + (size_t)row * KCLS * PP + (size_t)seg * CHUNK;
    const float* p1 = p0 + PP;
    const float* p2 = p0 + 2 * PP;
    const int*   tg = tgt + tbase;
    float*       ob = g_nll + tbase;

    int off0 = threadIdx.x * 4;
    int4   t4 = *(const int4*)(tg + off0);
    float4 a  = *(const float4*)(p0 + off0);
    float4 b  = *(const float4*)(p1 + off0);
    float4 c  = *(const float4*)(p2 + off0);

#pragma unroll
    for (int it = 0; it < ITERS; ++it) {
        int4 t4n; float4 an, bn, cn;
        if (it + 1 < ITERS) {
            int offn = (it + 1) * (THREADS * 4) + threadIdx.x * 4;
            t4n = *(const int4*)(tg + offn);
            an  = *(const float4*)(p0 + offn);
            bn  = *(const float4*)(p1 + offn);
            cn  = *(const float4*)(p2 + offn);
        }
        int off = it * (THREADS * 4) + threadIdx.x * 4;
        float4 o;
        o.x = nllsel(t4.x, a.x, b.x, c.x);
        o.y = nllsel(t4.y, a.y, b.y, c.y);
        o.z = nllsel(t4.z, a.z, b.z, c.z);
        o.w = nllsel(t4.w, a.w, b.w, c.w);
        atomicAdd(&sh[nbits(o.x) >> 19], 1u);
        atomicAdd(&sh[nbits(o.y) >> 19], 1u);
        atomicAdd(&sh[nbits(o.z) >> 19], 1u);
        atomicAdd(&sh[nbits(o.w) >> 19], 1u);
        *(float4*)(ob + off) = o;
        t4 = t4n; a = an; b = bn; c = cn;
    }
    __syncthreads();
    for (int i = threadIdx.x; i < NBIN; i += THREADS) {
        unsigned int v = sh[i];
        if (v) atomicAdd(&g_hist[row * NBIN + i], v);
    }
}

// -------- K2: per-row threshold bin via suffix scan (counts only) --------
__global__ void __launch_bounds__(THREADS) k2_thresh() {
    int row = blockIdx.x;
    __shared__ unsigned int sh[NBIN];
    __shared__ unsigned int cs[THREADS];
    for (int i = threadIdx.x; i < NBIN; i += THREADS)
        sh[i] = g_hist[row * NBIN + i];
    __syncthreads();
    unsigned s = 0;
    int base = threadIdx.x * (NBIN / THREADS);       // 16 bins each
    for (int j = 0; j < NBIN / THREADS; ++j) s += sh[base + j];
    cs[threadIdx.x] = s;
    __syncthreads();
    if (threadIdx.x == 0) {
        unsigned m = (unsigned)g_m;
        unsigned acc = 0, above = 0;
        int bstar = 0;
        for (int j = THREADS - 1; j >= 0; --j) {
            if (acc + cs[j] >= m) {
                for (int b = j * 16 + 15; b >= j * 16; --b) {
                    acc += sh[b];
                    if (acc >= m) { bstar = b; above = acc - sh[b]; break; }
                }
                break;
            }
            acc += cs[j];
        }
        g_bstar[row]  = bstar;
        g_needed[row] = (int)m - (int)above;
    }
}

// -------- K3: fx-sum above bins; block-private compaction of threshold bin --------
__global__ void __launch_bounds__(THREADS) k3_sum() {
    int row = blockIdx.x / CHUNKS;
    int seg = blockIdx.x % CHUNKS;
    unsigned bstar = (unsigned)g_bstar[row];
    size_t tbase = (size_t)row * PP + (size_t)seg * CHUNK;
    const float4* ib = (const float4*)(g_nll + tbase);
    float* sb = g_side + tbase;                      // private segment, capacity CHUNK

    __shared__ unsigned int scnt;
    if (threadIdx.x == 0) scnt = 0u;
    __syncthreads();

    // Front-batch all loads: 9 independent LDG.128 in flight per warp.
    float4 r[ITERS];
#pragma unroll
    for (int it = 0; it < ITERS; ++it)
        r[it] = ib[it * THREADS + threadIdx.x];

    unsigned long long fx = 0ull;
#pragma unroll
    for (int it = 0; it < ITERS; ++it) {
        float vv[4] = {r[it].x, r[it].y, r[it].z, r[it].w};
#pragma unroll
        for (int e = 0; e < 4; ++e) {
            float v = vv[e];
            unsigned bin = nbits(v) >> 19;
            if (bin > bstar) {
                fx += fx_of(v);
            } else if (bin == bstar) {               // rare (~2%); block-local atomic
                unsigned idx = atomicAdd(&scnt, 1u);
                sb[idx] = v;
            }
        }
    }

    __shared__ unsigned long long red[THREADS];
    red[threadIdx.x] = fx;
    __syncthreads();
    for (int st = THREADS / 2; st > 0; st >>= 1) {
        if (threadIdx.x < st) red[threadIdx.x] += red[threadIdx.x + st];
        __syncthreads();
    }
    if (threadIdx.x == 0) {
        if (red[0]) atomicAdd(&g_total, red[0] * TOT_MUL);
        g_segcnt[blockIdx.x] = scnt;
    }
}

// -------- K4: exact select inside the threshold bin (2 radix levels) --------
__global__ void __launch_bounds__(THREADS) k4_side() {
    int row = blockIdx.x;
    int needed = g_needed[row];
    if (needed <= 0) return;
    int tid = threadIdx.x;

    __shared__ unsigned int segc[CHUNKS];
    if (tid < CHUNKS) segc[tid] = g_segcnt[row * CHUNKS + tid];
    __syncthreads();

    __shared__ unsigned int h[NBIN];
    __shared__ unsigned int cs[THREADS];
    __shared__ unsigned long long red[THREADS];
    __shared__ unsigned int hb[128];
    __shared__ int s_b2, s_need2, s_b3, s_need3;

    for (int i = tid; i < NBIN; i += THREADS) h[i] = 0u;
    __syncthreads();
    for (int sg = 0; sg < CHUNKS; ++sg) {
        const float* sb = g_side + (size_t)(row * CHUNKS + sg) * CHUNK;
        int cnt = (int)segc[sg];
        for (int i = tid; i < cnt; i += THREADS) {
            unsigned bits = nbits(sb[i]);
            atomicAdd(&h[(bits >> 7) & 0xFFFu], 1u);
        }
    }
    __syncthreads();
    unsigned s = 0;
    int base = tid * (NBIN / THREADS);
    for (int j = 0; j < NBIN / THREADS; ++j) s += h[base + j];
    cs[tid] = s;
    __syncthreads();
    if (tid == 0) {
        unsigned acc = 0, above = 0; int b2 = 0;
        for (int j = THREADS - 1; j >= 0; --j) {
            if (acc + cs[j] >= (unsigned)needed) {
                for (int b = j * 16 + 15; b >= j * 16; --b) {
                    acc += h[b];
                    if (acc >= (unsigned)needed) { b2 = b; above = acc - h[b]; break; }
                }
                break;
            }
            acc += cs[j];
        }
        s_b2 = b2; s_need2 = needed - (int)above;
    }
    for (int i = tid; i < 128; i += THREADS) hb[i] = 0u;
    __syncthreads();
    int b2 = s_b2, need2 = s_need2;

    unsigned long long sum1 = 0ull;
    for (int sg = 0; sg < CHUNKS; ++sg) {
        const float* sb = g_side + (size_t)(row * CHUNKS + sg) * CHUNK;
        int cnt = (int)segc[sg];
        for (int i = tid; i < cnt; i += THREADS) {
            float v = sb[i];
            unsigned bits = nbits(v);
            int b = (int)((bits >> 7) & 0xFFFu);
            if (b > b2) sum1 += fx_of(v);
            else if (b == b2) atomicAdd(&hb[bits & 0x7Fu], 1u);
        }
    }
    red[tid] = sum1;
    __syncthreads();
    for (int st = THREADS / 2; st > 0; st >>= 1) {
        if (tid < st) red[tid] += red[tid + st];
        __syncthreads();
    }
    unsigned long long sum_gt2 = red[0];   // read by all before next barrier pass
    if (tid == 0) {
        unsigned acc = 0, above = 0; int b3 = 0;
        for (int b = 127; b >= 0; --b) {
            acc += hb[b];
            if (acc >= (unsigned)need2) { b3 = b; above = acc - hb[b]; break; }
        }
        s_b3 = b3; s_need3 = need2 - (int)above;
    }
    __syncthreads();
    int b3 = s_b3, need3 = s_need3;

    unsigned long long sum2 = 0ull;
    for (int sg = 0; sg < CHUNKS; ++sg) {
        const float* sb = g_side + (size_t)(row * CHUNKS + sg) * CHUNK;
        int cnt = (int)segc[sg];
        for (int i = tid; i < cnt; i += THREADS) {
            float v = sb[i];
            unsigned bits = nbits(v);
            if ((int)((bits >> 7) & 0xFFFu) == b2 && (int)(bits & 0x7Fu) > b3)
                sum2 += fx_of(v);
        }
    }
    red[tid] = sum2;
    __syncthreads();
    for (int st = THREADS / 2; st > 0; st >>= 1) {
        if (tid < st) red[tid] += red[tid + st];
        __syncthreads();
    }
    if (tid == 0) {
        unsigned tb = ((unsigned)g_bstar[row] << 19) | ((unsigned)b2 << 7) | (unsigned)b3;
        float tv = __uint_as_float(tb);
        unsigned long long contrib = sum_gt2 + red[0]
                                   + (unsigned long long)need3 * fx_of(tv);
        if (contrib) atomicAdd(&g_total, contrib * TOT_MUL);
    }
}

// -------- K5: finalize mean --------
__global__ void k5_final(float* out) {
    if (threadIdx.x == 0 && blockIdx.x == 0) {
        double tot = (double)g_total / FXD;
        out[0] = (float)(tot / ((double)ROWS * (double)g_m));
    }
}

extern "C" void kernel_launch(void* const* d_in, const int* in_sizes, int n_in,
                              void* d_out, int out_size) {
    const float* inp = (const float*)d_in[0];
    const int*   tgt = (const int*)d_in[1];
    const void*  sp  = (n_in > 2) ? d_in[2] : nullptr;
    (void)in_sizes; (void)out_size;

    k0_init<<<256, THREADS>>>(sp, (n_in > 2) ? 1 : 0);
    k1_nll<<<ROWS * CHUNKS, THREADS>>>(inp, tgt);
    k2_thresh<<<ROWS, THREADS>>>();
    k3_sum<<<ROWS * CHUNKS, THREADS>>>();
    k4_side<<<ROWS, THREADS>>>();
    k5_final<<<1, 32>>>((float*)d_out);
}